// round 1
// baseline (speedup 1.0000x reference)
#include <cuda_runtime.h>
#include <math.h>

#define BB   32768
#define DD   1024
#define NHEAD 8
#define HDIM 128
#define KTAP 4
#define EPSV 1e-6f
#define CAPV 15.0f

// ---------------- scratch (allocation-free, __device__ globals) ----------------
__device__ float g_xconv[(size_t)BB * DD];   // SiLU(conv tap)   134 MB
__device__ float g_z[(size_t)BB * DD];       // z projection     134 MB
__device__ float g_h[(size_t)BB * DD];       // h_norm           134 MB
__device__ float g_wlast[DD * DD];           // conv_w[:,:,K-1]    4 MB
__device__ float g_it[BB * NHEAD];
__device__ float g_ft[BB * NHEAD];
__device__ float g_og[BB * NHEAD];

// ---------------- pack last conv tap: wlast[o,i] = conv_w[o,i,K-1] -------------
__global__ void pack_w_kernel(const float* __restrict__ conv_w) {
    int i = blockIdx.x * blockDim.x + threadIdx.x;
    if (i < DD * DD) g_wlast[i] = conv_w[(size_t)i * KTAP + (KTAP - 1)];
}

// ---------------- tiled SGEMM: C[M,1024] = A[M,1024] * W[1024,1024]^T ----------
// Both A and W are K-contiguous (NT layout). BM=BN=128, BK=16, 256 thr, 8x8/thr.
// ACT: 0 = none, 1 = SiLU(y + bias)
template <int ACT>
__global__ void __launch_bounds__(256, 2)
gemm_nt_kernel(const float* __restrict__ A, const float* __restrict__ W,
               const float* __restrict__ bias, float* __restrict__ C) {
    __shared__ float As[16][132];
    __shared__ float Bs[16][132];

    const int m0 = blockIdx.y * 128;
    const int n0 = blockIdx.x * 128;
    const int t  = threadIdx.x;
    const int tx = t & 15;          // N direction
    const int ty = t >> 4;          // M direction

    float acc[8][8];
#pragma unroll
    for (int i = 0; i < 8; i++)
#pragma unroll
        for (int j = 0; j < 8; j++) acc[i][j] = 0.0f;

    for (int k0 = 0; k0 < 1024; k0 += 16) {
#pragma unroll
        for (int l = 0; l < 2; l++) {
            int f4  = t + l * 256;            // 0..511
            int row = f4 >> 2;                // 0..127
            int kc  = (f4 & 3) << 2;          // 0,4,8,12
            float4 av = *(const float4*)&A[(size_t)(m0 + row) * 1024 + k0 + kc];
            As[kc + 0][row] = av.x; As[kc + 1][row] = av.y;
            As[kc + 2][row] = av.z; As[kc + 3][row] = av.w;
            float4 bv = *(const float4*)&W[(size_t)(n0 + row) * 1024 + k0 + kc];
            Bs[kc + 0][row] = bv.x; Bs[kc + 1][row] = bv.y;
            Bs[kc + 2][row] = bv.z; Bs[kc + 3][row] = bv.w;
        }
        __syncthreads();

#pragma unroll
        for (int k = 0; k < 16; k++) {
            float a[8], b[8];
            *(float4*)(a)     = *(const float4*)&As[k][ty * 8];
            *(float4*)(a + 4) = *(const float4*)&As[k][ty * 8 + 4];
            *(float4*)(b)     = *(const float4*)&Bs[k][tx * 8];
            *(float4*)(b + 4) = *(const float4*)&Bs[k][tx * 8 + 4];
#pragma unroll
            for (int i = 0; i < 8; i++)
#pragma unroll
                for (int j = 0; j < 8; j++) acc[i][j] = fmaf(a[i], b[j], acc[i][j]);
        }
        __syncthreads();
    }

#pragma unroll
    for (int i = 0; i < 8; i++) {
        size_t row = (size_t)(m0 + ty * 8 + i);
#pragma unroll
        for (int j4 = 0; j4 < 2; j4++) {
            int col = n0 + tx * 8 + j4 * 4;
            float4 v;
            v.x = acc[i][j4 * 4 + 0]; v.y = acc[i][j4 * 4 + 1];
            v.z = acc[i][j4 * 4 + 2]; v.w = acc[i][j4 * 4 + 3];
            if (ACT == 1) {
                v.x += bias[col + 0]; v.y += bias[col + 1];
                v.z += bias[col + 2]; v.w += bias[col + 3];
                v.x = v.x / (1.0f + expf(-v.x));
                v.y = v.y / (1.0f + expf(-v.y));
                v.z = v.z / (1.0f + expf(-v.z));
                v.w = v.w / (1.0f + expf(-v.w));
            }
            *(float4*)&C[row * 1024 + col] = v;
        }
    }
}

// ---------------- gate GEMMs: i,f from x_conv; o from x; N=8 each --------------
// One warp per batch row; 8 accumulators per gate type per lane; float4 loads.
__device__ __forceinline__ float softcapf(float x) {
    return CAPV * tanhf(x * (1.0f / CAPV));
}

__global__ void gates_kernel(const float* __restrict__ X,
                             const float* __restrict__ iw, const float* __restrict__ ib,
                             const float* __restrict__ fw, const float* __restrict__ fb,
                             const float* __restrict__ ow, const float* __restrict__ ob) {
    const int w    = threadIdx.x >> 5;
    const int lane = threadIdx.x & 31;
    const int b    = blockIdx.x * 8 + w;

    const float* xr = X + (size_t)b * 1024;
    const float* xc = g_xconv + (size_t)b * 1024;

    float ai[8], af[8], ao[8];
#pragma unroll
    for (int g = 0; g < 8; g++) { ai[g] = 0.f; af[g] = 0.f; ao[g] = 0.f; }

#pragma unroll
    for (int it = 0; it < 8; it++) {
        int k = it * 128 + lane * 4;
        float4 xv = *(const float4*)&xr[k];
        float4 cv = *(const float4*)&xc[k];
#pragma unroll
        for (int g = 0; g < 8; g++) {
            float4 wi = *(const float4*)&iw[g * 1024 + k];
            ai[g] += cv.x * wi.x + cv.y * wi.y + cv.z * wi.z + cv.w * wi.w;
            float4 wf = *(const float4*)&fw[g * 1024 + k];
            af[g] += cv.x * wf.x + cv.y * wf.y + cv.z * wf.z + cv.w * wf.w;
            float4 wo = *(const float4*)&ow[g * 1024 + k];
            ao[g] += xv.x * wo.x + xv.y * wo.y + xv.z * wo.z + xv.w * wo.w;
        }
    }
#pragma unroll
    for (int g = 0; g < 8; g++) {
#pragma unroll
        for (int off = 16; off > 0; off >>= 1) {
            ai[g] += __shfl_xor_sync(0xffffffffu, ai[g], off);
            af[g] += __shfl_xor_sync(0xffffffffu, af[g], off);
            ao[g] += __shfl_xor_sync(0xffffffffu, ao[g], off);
        }
    }
    if (lane == 0) {
#pragma unroll
        for (int g = 0; g < 8; g++) {
            float vi = softcapf(ai[g] + ib[g]);
            float vf = softcapf(af[g] + fb[g]);
            float vo = softcapf(ao[g] + ob[g]);
            g_it[b * 8 + g] = vi;
            g_ft[b * 8 + g] = vf;
            g_og[b * 8 + g] = 1.0f / (1.0f + expf(-vo));
        }
    }
}

// ---------------- gating + per-head LayerNorm ----------------------------------
// One block per batch row; warp h owns head h (H=128, 4 elems/lane).
__global__ void elem_kernel(const float* __restrict__ c, const float* __restrict__ n,
                            const float* __restrict__ m,
                            const float* __restrict__ gw, const float* __restrict__ gb,
                            float* __restrict__ c_out, float* __restrict__ n_out,
                            float* __restrict__ m_out) {
    const int b    = blockIdx.x;
    const int h    = threadIdx.x >> 5;
    const int lane = threadIdx.x & 31;
    const int bh   = b * NHEAD + h;

    float it  = g_it[bh];
    float ft  = g_ft[bh];
    float og  = g_og[bh];
    float m0  = m[bh];
    float fl  = -log1pf(expf(-ft));           // log(sigmoid(f)), |ft|<=15 so safe
    float mn  = fmaxf(fl + m0, it);
    float ig  = expf(it - mn);
    float fg  = expf(fl + m0 - mn);

    size_t base = (size_t)b * 1024 + (size_t)h * 128;

    float hv[4];
    float s = 0.f, sq = 0.f;
#pragma unroll
    for (int j = 0; j < 4; j++) {
        int e = lane + 32 * j;
        float cn = fg * c[base + e] + ig * g_z[base + e];
        float nn = fg * n[base + e] + ig;
        c_out[base + e] = cn;
        n_out[base + e] = nn;
        float x = og * cn / (nn + EPSV);
        hv[j] = x;
        s  += x;
        sq += x * x;
    }
#pragma unroll
    for (int off = 16; off > 0; off >>= 1) {
        s  += __shfl_xor_sync(0xffffffffu, s,  off);
        sq += __shfl_xor_sync(0xffffffffu, sq, off);
    }
    float mu  = s * (1.0f / 128.0f);
    float var = sq * (1.0f / 128.0f) - mu * mu;
    float rs  = rsqrtf(var + EPSV);
#pragma unroll
    for (int j = 0; j < 4; j++) {
        int e = lane + 32 * j;
        g_h[base + e] = (hv[j] - mu) * rs * gw[h * 128 + e] + gb[h * 128 + e];
    }
    if (lane == 0) m_out[bh] = mn;
}

// ---------------- launch --------------------------------------------------------
extern "C" void kernel_launch(void* const* d_in, const int* in_sizes, int n_in,
                              void* d_out, int out_size) {
    const float* x      = (const float*)d_in[0];
    const float* c      = (const float*)d_in[1];
    const float* n      = (const float*)d_in[2];
    const float* m      = (const float*)d_in[3];
    const float* conv_w = (const float*)d_in[4];
    const float* conv_b = (const float*)d_in[5];
    const float* z_w    = (const float*)d_in[6];
    const float* i_w    = (const float*)d_in[7];
    const float* i_b    = (const float*)d_in[8];
    const float* f_w    = (const float*)d_in[9];
    const float* f_b    = (const float*)d_in[10];
    const float* o_w    = (const float*)d_in[11];
    const float* o_b    = (const float*)d_in[12];
    const float* gn_w   = (const float*)d_in[13];
    const float* gn_b   = (const float*)d_in[14];
    const float* out_w  = (const float*)d_in[15];

    // Output packing: (out[B,D], c_new[B,NH,H], n_new[B,NH,H], m_new[B,NH]) concat.
    float* out   = (float*)d_out;
    float* c_out = out   + (size_t)BB * DD;
    float* n_out = c_out + (size_t)BB * DD;
    float* m_out = n_out + (size_t)BB * DD;

    float *p_wlast, *p_xconv, *p_z, *p_h;
    cudaGetSymbolAddress((void**)&p_wlast, g_wlast);
    cudaGetSymbolAddress((void**)&p_xconv, g_xconv);
    cudaGetSymbolAddress((void**)&p_z,     g_z);
    cudaGetSymbolAddress((void**)&p_h,     g_h);

    pack_w_kernel<<<(DD * DD) / 256, 256>>>(conv_w);

    dim3 gg(1024 / 128, BB / 128);   // (8, 256)
    gemm_nt_kernel<1><<<gg, 256>>>(x,   p_wlast, conv_b, p_xconv);  // SiLU(conv)
    gemm_nt_kernel<0><<<gg, 256>>>(x,   z_w,     nullptr, p_z);     // z
    gates_kernel<<<BB / 8, 256>>>(x, i_w, i_b, f_w, f_b, o_w, o_b);
    elem_kernel<<<BB, 256>>>(c, n, m, gn_w, gn_b, c_out, n_out, m_out);
    gemm_nt_kernel<0><<<gg, 256>>>(p_h, out_w,   nullptr, out);     // out proj
}

// round 5
// speedup vs baseline: 3.2409x; 3.2409x over previous
#include <cuda_runtime.h>
#include <cuda_bf16.h>
#include <math.h>
#include <stdint.h>

#define BB   32768
#define DD   1024
#define NHEAD 8
#define KTAP 4
#define EPSV 1e-6f
#define CAPV 15.0f

// ---------------- scratch (allocation-free, __device__ globals) ----------------
__device__ float g_xconv[(size_t)BB * DD];                 // SiLU(conv tap) fp32
__device__ float g_z[(size_t)BB * DD];                     // z projection fp32
__device__ __nv_bfloat16 g_xhi[(size_t)BB * DD];
__device__ __nv_bfloat16 g_xlo[(size_t)BB * DD];
__device__ __nv_bfloat16 g_hhi[(size_t)BB * DD];
__device__ __nv_bfloat16 g_hlo[(size_t)BB * DD];
__device__ __nv_bfloat16 g_wc_hi[DD * DD], g_wc_lo[DD * DD];
__device__ __nv_bfloat16 g_wz_hi[DD * DD], g_wz_lo[DD * DD];
__device__ __nv_bfloat16 g_wo_hi[DD * DD], g_wo_lo[DD * DD];
__device__ float g_it[BB * NHEAD];
__device__ float g_ft[BB * NHEAD];
__device__ float g_og[BB * NHEAD];

// ================= low-level helpers (arch-portable, sm_80+) ===================
__device__ __forceinline__ uint32_t smem_u32(const void* p) {
    uint32_t a;
    asm("{ .reg .u64 t; cvta.to.shared.u64 t, %1; cvt.u32.u64 %0, t; }" : "=r"(a) : "l"(p));
    return a;
}
__device__ __forceinline__ void cp16(uint32_t dst, const void* src) {
    asm volatile("cp.async.cg.shared.global [%0], [%1], 16;" :: "r"(dst), "l"(src));
}
__device__ __forceinline__ void cp_commit() {
    asm volatile("cp.async.commit_group;" ::: "memory");
}
__device__ __forceinline__ void cp_wait2() {
    asm volatile("cp.async.wait_group 2;" ::: "memory");
}
__device__ __forceinline__ void ldsm4(uint32_t* r, uint32_t addr) {
    asm volatile("ldmatrix.sync.aligned.m8n8.x4.shared.b16 {%0,%1,%2,%3}, [%4];"
                 : "=r"(r[0]), "=r"(r[1]), "=r"(r[2]), "=r"(r[3]) : "r"(addr));
}
__device__ __forceinline__ void mma_bf16(float* d, const uint32_t* a, const uint32_t* b) {
    asm volatile(
        "mma.sync.aligned.m16n8k16.row.col.f32.bf16.bf16.f32 "
        "{%0,%1,%2,%3}, {%4,%5,%6,%7}, {%8,%9}, {%0,%1,%2,%3};"
        : "+f"(d[0]), "+f"(d[1]), "+f"(d[2]), "+f"(d[3])
        : "r"(a[0]), "r"(a[1]), "r"(a[2]), "r"(a[3]), "r"(b[0]), "r"(b[1]));
}

// ================= split kernels (fp32 -> bf16 hi + bf16 lo) ===================
__global__ void split_kernel(const float* __restrict__ in, __nv_bfloat16* __restrict__ hi,
                             __nv_bfloat16* __restrict__ lo, int n4) {
    int i = blockIdx.x * blockDim.x + threadIdx.x;
    if (i >= n4) return;
    float4 v = ((const float4*)in)[i];
    __nv_bfloat16 h0 = __float2bfloat16(v.x), h1 = __float2bfloat16(v.y);
    __nv_bfloat16 h2 = __float2bfloat16(v.z), h3 = __float2bfloat16(v.w);
    __nv_bfloat162 p0, p1, q0, q1;
    p0.x = h0; p0.y = h1; p1.x = h2; p1.y = h3;
    q0.x = __float2bfloat16(v.x - __bfloat162float(h0));
    q0.y = __float2bfloat16(v.y - __bfloat162float(h1));
    q1.x = __float2bfloat16(v.z - __bfloat162float(h2));
    q1.y = __float2bfloat16(v.w - __bfloat162float(h3));
    ((__nv_bfloat162*)hi)[i * 2]     = p0;
    ((__nv_bfloat162*)hi)[i * 2 + 1] = p1;
    ((__nv_bfloat162*)lo)[i * 2]     = q0;
    ((__nv_bfloat162*)lo)[i * 2 + 1] = q1;
}

__global__ void split_conv_kernel(const float* __restrict__ conv_w) {
    int i = blockIdx.x * blockDim.x + threadIdx.x;
    if (i >= DD * DD) return;
    float v = conv_w[(size_t)i * KTAP + (KTAP - 1)];
    __nv_bfloat16 h = __float2bfloat16(v);
    g_wc_hi[i] = h;
    g_wc_lo[i] = __float2bfloat16(v - __bfloat162float(h));
}

// ================= tensor-core GEMM via mma.sync (split-bf16, 3 MMAs) ==========
// C[M,1024] = A[M,1024] * W[1024,1024]^T, A/W given as bf16 hi+lo pairs.
// Block 128x128, BK=32, 3-stage cp.async pipeline, 8 warps as 2(M) x 4(N),
// warp tile 64x32 => 4 M-tiles x 4 N-tiles of m16n8k16. ACT: 1 = SiLU(y+bias).
#define TSTRIDE     80                    // bytes per smem row (64 data + 16 pad)
#define TENSOR_B    (128 * TSTRIDE)       // 10240 bytes per operand tensor
#define STAGE_B     (4 * TENSOR_B)        // Ahi, Alo, Whi, Wlo
#define NSTAGE      3
#define GEMM_SMEM   (NSTAGE * STAGE_B)    // 122880 bytes

template <int ACT>
__global__ void __launch_bounds__(256)
gemm_mma_kernel(const __nv_bfloat16* __restrict__ Ahi, const __nv_bfloat16* __restrict__ Alo,
                const __nv_bfloat16* __restrict__ Whi, const __nv_bfloat16* __restrict__ Wlo,
                const float* __restrict__ bias, float* __restrict__ C) {
    extern __shared__ char dynsmem[];
    const uint32_t sbase = smem_u32(dynsmem);

    const int t      = threadIdx.x;
    const int lane   = t & 31;
    const int wid    = t >> 5;
    const int warp_m = wid >> 2;          // 0..1
    const int warp_n = wid & 3;           // 0..3
    const int m0     = blockIdx.y * 128;
    const int n0     = blockIdx.x * 128;

    const char* srcs[4];
    srcs[0] = (const char*)(Ahi + (size_t)m0 * DD);
    srcs[1] = (const char*)(Alo + (size_t)m0 * DD);
    srcs[2] = (const char*)(Whi + (size_t)n0 * DD);
    srcs[3] = (const char*)(Wlo + (size_t)n0 * DD);

    // per-thread load slots: 2048 16B chunks per stage, 8 per thread
    int l_tensor[8], l_row[8], l_ch[8];
#pragma unroll
    for (int j = 0; j < 8; j++) {
        int cid = t + j * 256;
        l_tensor[j] = cid >> 9;
        int rc = cid & 511;
        l_row[j] = rc >> 2;
        l_ch[j]  = rc & 3;
    }

    auto load_stage = [&](int stg, int kiter) {
        uint32_t sdst = sbase + stg * STAGE_B;
        int k0b = kiter * 64;   // 32 bf16 = 64 bytes along K
#pragma unroll
        for (int j = 0; j < 8; j++) {
            uint32_t dst = sdst + l_tensor[j] * TENSOR_B + l_row[j] * TSTRIDE + l_ch[j] * 16;
            const char* src = srcs[l_tensor[j]] + (size_t)l_row[j] * 2048 + k0b + l_ch[j] * 16;
            cp16(dst, src);
        }
    };

    float acc[4][4][4];
#pragma unroll
    for (int i = 0; i < 4; i++)
#pragma unroll
        for (int j = 0; j < 4; j++)
#pragma unroll
            for (int q = 0; q < 4; q++) acc[i][j][q] = 0.0f;

    // ldmatrix base offsets (within a stage)
    const uint32_t offA = (uint32_t)((warp_m * 64 + (lane & 15)) * TSTRIDE + (lane >> 4) * 16);
    const uint32_t offB = (uint32_t)(2 * TENSOR_B
                        + (warp_n * 32 + ((lane >> 4) << 3) + (lane & 7)) * TSTRIDE
                        + (((lane >> 3) & 1) << 4));

    load_stage(0, 0); cp_commit();
    load_stage(1, 1); cp_commit();

    for (int i = 0; i < 32; i++) {
        __syncthreads();                       // buffer (i+2)%3 free to overwrite
        if (i + 2 < 32) load_stage((i + 2) % NSTAGE, i + 2);
        cp_commit();
        cp_wait2();
        __syncthreads();

        const uint32_t stg = sbase + (i % NSTAGE) * STAGE_B;
#pragma unroll
        for (int k16 = 0; k16 < 2; k16++) {
            const uint32_t koff = k16 * 32;
            uint32_t ah[4][4], al[4][4], bh[2][4], bl[2][4];
#pragma unroll
            for (int mt = 0; mt < 4; mt++) {
                ldsm4(ah[mt], stg + offA + mt * (16 * TSTRIDE) + koff);
                ldsm4(al[mt], stg + offA + TENSOR_B + mt * (16 * TSTRIDE) + koff);
            }
#pragma unroll
            for (int p = 0; p < 2; p++) {
                ldsm4(bh[p], stg + offB + p * (16 * TSTRIDE) + koff);
                ldsm4(bl[p], stg + offB + TENSOR_B + p * (16 * TSTRIDE) + koff);
            }
#pragma unroll
            for (int mt = 0; mt < 4; mt++)
#pragma unroll
                for (int nt = 0; nt < 4; nt++) {
                    const uint32_t* bhp = &bh[nt >> 1][(nt & 1) * 2];
                    const uint32_t* blp = &bl[nt >> 1][(nt & 1) * 2];
                    mma_bf16(acc[mt][nt], ah[mt], bhp);   // hi*hi
                    mma_bf16(acc[mt][nt], ah[mt], blp);   // hi*lo
                    mma_bf16(acc[mt][nt], al[mt], bhp);   // lo*hi
                }
        }
    }

    // epilogue straight from fragments
    const int g  = lane >> 2;
    const int tg = lane & 3;
#pragma unroll
    for (int mt = 0; mt < 4; mt++) {
#pragma unroll
        for (int nt = 0; nt < 4; nt++) {
            int col  = n0 + warp_n * 32 + nt * 8 + tg * 2;
            int rowa = m0 + warp_m * 64 + mt * 16 + g;
            float2 v0, v1;
            v0.x = acc[mt][nt][0]; v0.y = acc[mt][nt][1];
            v1.x = acc[mt][nt][2]; v1.y = acc[mt][nt][3];
            if (ACT == 1) {
                float b0 = bias[col], b1 = bias[col + 1];
                v0.x += b0; v0.y += b1; v1.x += b0; v1.y += b1;
                v0.x = v0.x / (1.0f + expf(-v0.x));
                v0.y = v0.y / (1.0f + expf(-v0.y));
                v1.x = v1.x / (1.0f + expf(-v1.x));
                v1.y = v1.y / (1.0f + expf(-v1.y));
            }
            *(float2*)&C[(size_t)rowa * DD + col]       = v0;
            *(float2*)&C[(size_t)(rowa + 8) * DD + col] = v1;
        }
    }
}

// ---------------- gate GEMMs: i,f from x_conv; o from x; N=8 each --------------
__device__ __forceinline__ float softcapf(float x) {
    return CAPV * tanhf(x * (1.0f / CAPV));
}

__global__ void gates_kernel(const float* __restrict__ X,
                             const float* __restrict__ iw, const float* __restrict__ ib,
                             const float* __restrict__ fw, const float* __restrict__ fb,
                             const float* __restrict__ ow, const float* __restrict__ ob) {
    const int w    = threadIdx.x >> 5;
    const int lane = threadIdx.x & 31;
    const int b    = blockIdx.x * 8 + w;

    const float* xr = X + (size_t)b * 1024;
    const float* xc = g_xconv + (size_t)b * 1024;

    float ai[8], af[8], ao[8];
#pragma unroll
    for (int g = 0; g < 8; g++) { ai[g] = 0.f; af[g] = 0.f; ao[g] = 0.f; }

#pragma unroll
    for (int it = 0; it < 8; it++) {
        int k = it * 128 + lane * 4;
        float4 xv = *(const float4*)&xr[k];
        float4 cv = *(const float4*)&xc[k];
#pragma unroll
        for (int g = 0; g < 8; g++) {
            float4 wi = *(const float4*)&iw[g * 1024 + k];
            ai[g] += cv.x * wi.x + cv.y * wi.y + cv.z * wi.z + cv.w * wi.w;
            float4 wf = *(const float4*)&fw[g * 1024 + k];
            af[g] += cv.x * wf.x + cv.y * wf.y + cv.z * wf.z + cv.w * wf.w;
            float4 wo = *(const float4*)&ow[g * 1024 + k];
            ao[g] += xv.x * wo.x + xv.y * wo.y + xv.z * wo.z + xv.w * wo.w;
        }
    }
#pragma unroll
    for (int g = 0; g < 8; g++) {
#pragma unroll
        for (int off = 16; off > 0; off >>= 1) {
            ai[g] += __shfl_xor_sync(0xffffffffu, ai[g], off);
            af[g] += __shfl_xor_sync(0xffffffffu, af[g], off);
            ao[g] += __shfl_xor_sync(0xffffffffu, ao[g], off);
        }
    }
    if (lane == 0) {
#pragma unroll
        for (int g = 0; g < 8; g++) {
            float vi = softcapf(ai[g] + ib[g]);
            float vf = softcapf(af[g] + fb[g]);
            float vo = softcapf(ao[g] + ob[g]);
            g_it[b * 8 + g] = vi;
            g_ft[b * 8 + g] = vf;
            g_og[b * 8 + g] = 1.0f / (1.0f + expf(-vo));
        }
    }
}

// ---------------- gating + per-head LayerNorm (emits h as bf16 hi/lo) ----------
__global__ void elem_kernel(const float* __restrict__ c, const float* __restrict__ n,
                            const float* __restrict__ m,
                            const float* __restrict__ gw, const float* __restrict__ gb,
                            float* __restrict__ c_out, float* __restrict__ n_out,
                            float* __restrict__ m_out) {
    const int b    = blockIdx.x;
    const int h    = threadIdx.x >> 5;
    const int lane = threadIdx.x & 31;
    const int bh   = b * NHEAD + h;

    float it  = g_it[bh];
    float ft  = g_ft[bh];
    float og  = g_og[bh];
    float m0  = m[bh];
    float fl  = -log1pf(expf(-ft));
    float mn  = fmaxf(fl + m0, it);
    float ig  = expf(it - mn);
    float fg  = expf(fl + m0 - mn);

    size_t base = (size_t)b * 1024 + (size_t)h * 128;

    float hv[4];
    float s = 0.f, sq = 0.f;
#pragma unroll
    for (int j = 0; j < 4; j++) {
        int e = lane + 32 * j;
        float cn = fg * c[base + e] + ig * g_z[base + e];
        float nn = fg * n[base + e] + ig;
        c_out[base + e] = cn;
        n_out[base + e] = nn;
        float x = og * cn / (nn + EPSV);
        hv[j] = x;
        s  += x;
        sq += x * x;
    }
#pragma unroll
    for (int off = 16; off > 0; off >>= 1) {
        s  += __shfl_xor_sync(0xffffffffu, s,  off);
        sq += __shfl_xor_sync(0xffffffffu, sq, off);
    }
    float mu  = s * (1.0f / 128.0f);
    float var = sq * (1.0f / 128.0f) - mu * mu;
    float rs  = rsqrtf(var + EPSV);
#pragma unroll
    for (int j = 0; j < 4; j++) {
        int e = lane + 32 * j;
        float hn = (hv[j] - mu) * rs * gw[h * 128 + e] + gb[h * 128 + e];
        __nv_bfloat16 hh = __float2bfloat16(hn);
        g_hhi[base + e] = hh;
        g_hlo[base + e] = __float2bfloat16(hn - __bfloat162float(hh));
    }
    if (lane == 0) m_out[bh] = mn;
}

// ---------------- launch --------------------------------------------------------
extern "C" void kernel_launch(void* const* d_in, const int* in_sizes, int n_in,
                              void* d_out, int out_size) {
    const float* x      = (const float*)d_in[0];
    const float* c      = (const float*)d_in[1];
    const float* n      = (const float*)d_in[2];
    const float* m      = (const float*)d_in[3];
    const float* conv_w = (const float*)d_in[4];
    const float* conv_b = (const float*)d_in[5];
    const float* z_w    = (const float*)d_in[6];
    const float* i_w    = (const float*)d_in[7];
    const float* i_b    = (const float*)d_in[8];
    const float* f_w    = (const float*)d_in[9];
    const float* f_b    = (const float*)d_in[10];
    const float* o_w    = (const float*)d_in[11];
    const float* o_b    = (const float*)d_in[12];
    const float* gn_w   = (const float*)d_in[13];
    const float* gn_b   = (const float*)d_in[14];
    const float* out_w  = (const float*)d_in[15];

    float* out   = (float*)d_out;
    float* c_out = out   + (size_t)BB * DD;
    float* n_out = c_out + (size_t)BB * DD;
    float* m_out = n_out + (size_t)BB * DD;

    __nv_bfloat16 *p_xhi, *p_xlo, *p_hhi, *p_hlo;
    __nv_bfloat16 *p_wchi, *p_wclo, *p_wzhi, *p_wzlo, *p_wohi, *p_wolo;
    float *p_xconv, *p_z;
    cudaGetSymbolAddress((void**)&p_xhi,   g_xhi);
    cudaGetSymbolAddress((void**)&p_xlo,   g_xlo);
    cudaGetSymbolAddress((void**)&p_hhi,   g_hhi);
    cudaGetSymbolAddress((void**)&p_hlo,   g_hlo);
    cudaGetSymbolAddress((void**)&p_wchi,  g_wc_hi);
    cudaGetSymbolAddress((void**)&p_wclo,  g_wc_lo);
    cudaGetSymbolAddress((void**)&p_wzhi,  g_wz_hi);
    cudaGetSymbolAddress((void**)&p_wzlo,  g_wz_lo);
    cudaGetSymbolAddress((void**)&p_wohi,  g_wo_hi);
    cudaGetSymbolAddress((void**)&p_wolo,  g_wo_lo);
    cudaGetSymbolAddress((void**)&p_xconv, g_xconv);
    cudaGetSymbolAddress((void**)&p_z,     g_z);

    cudaFuncSetAttribute(gemm_mma_kernel<0>, cudaFuncAttributeMaxDynamicSharedMemorySize, GEMM_SMEM);
    cudaFuncSetAttribute(gemm_mma_kernel<1>, cudaFuncAttributeMaxDynamicSharedMemorySize, GEMM_SMEM);

    split_kernel<<<(BB * DD / 4 + 255) / 256, 256>>>(x, p_xhi, p_xlo, BB * DD / 4);
    split_conv_kernel<<<(DD * DD + 255) / 256, 256>>>(conv_w);
    split_kernel<<<(DD * DD / 4 + 255) / 256, 256>>>(z_w,   p_wzhi, p_wzlo, DD * DD / 4);
    split_kernel<<<(DD * DD / 4 + 255) / 256, 256>>>(out_w, p_wohi, p_wolo, DD * DD / 4);

    dim3 gg(DD / 128, BB / 128);   // (8, 256)
    gemm_mma_kernel<1><<<gg, 256, GEMM_SMEM>>>(p_xhi, p_xlo, p_wchi, p_wclo, conv_b, p_xconv);
    gemm_mma_kernel<0><<<gg, 256, GEMM_SMEM>>>(p_xhi, p_xlo, p_wzhi, p_wzlo, nullptr, p_z);
    gates_kernel<<<BB / 8, 256>>>(x, i_w, i_b, f_w, f_b, o_w, o_b);
    elem_kernel<<<BB, 256>>>(c, n, m, gn_w, gn_b, c_out, n_out, m_out);
    gemm_mma_kernel<0><<<gg, 256, GEMM_SMEM>>>(p_hhi, p_hlo, p_wohi, p_wolo, nullptr, out);
}

// round 8
// speedup vs baseline: 4.8726x; 1.5035x over previous
#include <cuda_runtime.h>
#include <cuda_fp16.h>
#include <math.h>
#include <stdint.h>

#define BB   32768
#define DD   1024
#define NHEAD 8
#define KTAP 4
#define EPSV 1e-6f
#define CAPV 15.0f

// ---------------- scratch (allocation-free, __device__ globals) ----------------
__device__ __half g_xh[(size_t)BB * DD];     // x as fp16
__device__ __half g_xch[(size_t)BB * DD];    // SiLU(conv tap) as fp16
__device__ float  g_z[(size_t)BB * DD];      // z projection fp32
__device__ __half g_hh[(size_t)BB * DD];     // h_norm as fp16
__device__ __half g_wc_hi[DD * DD], g_wc_lo[DD * DD];   // conv last tap (lo x1024)
__device__ __half g_wz_hi[DD * DD], g_wz_lo[DD * DD];
__device__ __half g_wo_hi[DD * DD], g_wo_lo[DD * DD];
__device__ float g_it[BB * NHEAD];
__device__ float g_ft[BB * NHEAD];
__device__ float g_og[BB * NHEAD];

// ================= low-level helpers (arch-portable, sm_80+) ===================
__device__ __forceinline__ uint32_t smem_u32(const void* p) {
    uint32_t a;
    asm("{ .reg .u64 t; cvta.to.shared.u64 t, %1; cvt.u32.u64 %0, t; }" : "=r"(a) : "l"(p));
    return a;
}
__device__ __forceinline__ void cp16(uint32_t dst, const void* src) {
    asm volatile("cp.async.cg.shared.global [%0], [%1], 16;" :: "r"(dst), "l"(src));
}
__device__ __forceinline__ void cp_commit() {
    asm volatile("cp.async.commit_group;" ::: "memory");
}
__device__ __forceinline__ void cp_wait1() {
    asm volatile("cp.async.wait_group 1;" ::: "memory");
}
__device__ __forceinline__ void cp_wait0() {
    asm volatile("cp.async.wait_group 0;" ::: "memory");
}
__device__ __forceinline__ void ldsm4(uint32_t* r, uint32_t addr) {
    asm volatile("ldmatrix.sync.aligned.m8n8.x4.shared.b16 {%0,%1,%2,%3}, [%4];"
                 : "=r"(r[0]), "=r"(r[1]), "=r"(r[2]), "=r"(r[3]) : "r"(addr));
}
__device__ __forceinline__ void mma_f16(float* d, const uint32_t* a, const uint32_t* b) {
    asm volatile(
        "mma.sync.aligned.m16n8k16.row.col.f32.f16.f16.f32 "
        "{%0,%1,%2,%3}, {%4,%5,%6,%7}, {%8,%9}, {%0,%1,%2,%3};"
        : "+f"(d[0]), "+f"(d[1]), "+f"(d[2]), "+f"(d[3])
        : "r"(a[0]), "r"(a[1]), "r"(a[2]), "r"(a[3]), "r"(b[0]), "r"(b[1]));
}

// ================= conversion / split kernels ==================================
__global__ void tohalf_kernel(const float* __restrict__ in, __half* __restrict__ out, int n8) {
    int i = blockIdx.x * blockDim.x + threadIdx.x;
    if (i >= n8) return;
    float4 a = ((const float4*)in)[i * 2];
    float4 b = ((const float4*)in)[i * 2 + 1];
    __half2 h[4];
    h[0] = __floats2half2_rn(a.x, a.y);
    h[1] = __floats2half2_rn(a.z, a.w);
    h[2] = __floats2half2_rn(b.x, b.y);
    h[3] = __floats2half2_rn(b.z, b.w);
    ((uint4*)out)[i] = *(uint4*)h;
}

__global__ void wsplit_kernel(const float* __restrict__ w, __half* __restrict__ hi,
                              __half* __restrict__ lo, int n) {
    int i = blockIdx.x * blockDim.x + threadIdx.x;
    if (i >= n) return;
    float v = w[i];
    __half h = __float2half_rn(v);
    hi[i] = h;
    lo[i] = __float2half_rn((v - __half2float(h)) * 1024.0f);
}

__global__ void wsplit_conv_kernel(const float* __restrict__ conv_w) {
    int i = blockIdx.x * blockDim.x + threadIdx.x;
    if (i >= DD * DD) return;
    float v = conv_w[(size_t)i * KTAP + (KTAP - 1)];
    __half h = __float2half_rn(v);
    g_wc_hi[i] = h;
    g_wc_lo[i] = __float2half_rn((v - __half2float(h)) * 1024.0f);
}

// ================= tensor-core GEMM (fp16 2-term: Ah*Whi + (Ah/2^10)*(Wlo*2^10))
// C[M,1024] = A[M,1024] * W[1024,1024]^T. Block 128x128, BK=32, 2 stages,
// 2 CTAs/SM. 8 warps as 2(M) x 4(N), warp tile 64x32.
// ACT 0: plain fp32 out.  ACT 1: SiLU(y+bias), fp16 out.
#define TSTRIDE   80                      // 64B data + 16B pad
#define TENSOR_B  (128 * TSTRIDE)         // 10240
#define STAGE_B   (3 * TENSOR_B)          // Ah, Whi, Wlo
#define NSTAGE    2
#define GEMM_SMEM (NSTAGE * STAGE_B)      // 61440

template <int ACT>
__global__ void __launch_bounds__(256, 2)
gemm2_kernel(const __half* __restrict__ Ah, const __half* __restrict__ Whi,
             const __half* __restrict__ Wlo, const float* __restrict__ bias,
             void* __restrict__ Cout) {
    extern __shared__ char dynsmem[];
    const uint32_t sbase = smem_u32(dynsmem);

    const int t      = threadIdx.x;
    const int lane   = t & 31;
    const int wid    = t >> 5;
    const int warp_m = wid >> 2;
    const int warp_n = wid & 3;
    const int m0     = blockIdx.y * 128;
    const int n0     = blockIdx.x * 128;

    const char* srcs[3];
    srcs[0] = (const char*)(Ah  + (size_t)m0 * DD);
    srcs[1] = (const char*)(Whi + (size_t)n0 * DD);
    srcs[2] = (const char*)(Wlo + (size_t)n0 * DD);

    // 1536 16B chunks per stage, 6 per thread
    int l_tensor[6], l_row[6], l_ch[6];
#pragma unroll
    for (int j = 0; j < 6; j++) {
        int cid = t + j * 256;
        l_tensor[j] = cid >> 9;
        int rc = cid & 511;
        l_row[j] = rc >> 2;
        l_ch[j]  = rc & 3;
    }

    auto load_stage = [&](int stg, int kiter) {
        uint32_t sdst = sbase + stg * STAGE_B;
        int k0b = kiter * 64;                 // 32 fp16 = 64B along K
#pragma unroll
        for (int j = 0; j < 6; j++) {
            uint32_t dst = sdst + l_tensor[j] * TENSOR_B + l_row[j] * TSTRIDE + l_ch[j] * 16;
            const char* src = srcs[l_tensor[j]] + (size_t)l_row[j] * 2048 + k0b + l_ch[j] * 16;
            cp16(dst, src);
        }
    };

    float acc[4][4][4];
#pragma unroll
    for (int i = 0; i < 4; i++)
#pragma unroll
        for (int j = 0; j < 4; j++)
#pragma unroll
            for (int q = 0; q < 4; q++) acc[i][j][q] = 0.0f;

    const uint32_t offA = (uint32_t)((warp_m * 64 + (lane & 15)) * TSTRIDE + (lane >> 4) * 16);
    const uint32_t offB = (uint32_t)((warp_n * 32 + ((lane >> 4) << 3) + (lane & 7)) * TSTRIDE
                        + (((lane >> 3) & 1) << 4));
    const __half2 dscale = __float2half2_rn(0.0009765625f);   // 2^-10 exact

    load_stage(0, 0);
    cp_commit();

    for (int i = 0; i < 32; i++) {
        __syncthreads();                  // stage (i+1)&1 fully consumed at iter i-1
        if (i + 1 < 32) {
            load_stage((i + 1) & 1, i + 1);
            cp_commit();
            cp_wait1();                   // own copies for stage i&1 done
        } else {
            cp_wait0();
        }
        __syncthreads();                  // all threads' copies visible

        const uint32_t stg = sbase + (i & 1) * STAGE_B;
#pragma unroll
        for (int k16 = 0; k16 < 2; k16++) {
            const uint32_t koff = k16 * 32;
            uint32_t bh[2][4], bl[2][4];
#pragma unroll
            for (int p = 0; p < 2; p++) {
                ldsm4(bh[p], stg + TENSOR_B     + offB + p * (16 * TSTRIDE) + koff);
                ldsm4(bl[p], stg + 2 * TENSOR_B + offB + p * (16 * TSTRIDE) + koff);
            }
#pragma unroll
            for (int mt = 0; mt < 4; mt++) {
                uint32_t ah[4], as[4];
                ldsm4(ah, stg + offA + mt * (16 * TSTRIDE) + koff);
#pragma unroll
                for (int q = 0; q < 4; q++) {
                    __half2 hv = __hmul2(*(__half2*)&ah[q], dscale);
                    as[q] = *(uint32_t*)&hv;
                }
#pragma unroll
                for (int nt = 0; nt < 4; nt++) {
                    const uint32_t* bhp = &bh[nt >> 1][(nt & 1) * 2];
                    const uint32_t* blp = &bl[nt >> 1][(nt & 1) * 2];
                    mma_f16(acc[mt][nt], ah, bhp);
                    mma_f16(acc[mt][nt], as, blp);
                }
            }
        }
    }

    // epilogue straight from fragments
    const int g  = lane >> 2;
    const int tg = lane & 3;
#pragma unroll
    for (int mt = 0; mt < 4; mt++) {
#pragma unroll
        for (int nt = 0; nt < 4; nt++) {
            int col  = n0 + warp_n * 32 + nt * 8 + tg * 2;
            int rowa = m0 + warp_m * 64 + mt * 16 + g;
            float2 v0, v1;
            v0.x = acc[mt][nt][0]; v0.y = acc[mt][nt][1];
            v1.x = acc[mt][nt][2]; v1.y = acc[mt][nt][3];
            if (ACT == 1) {
                float b0 = bias[col], b1 = bias[col + 1];
                v0.x += b0; v0.y += b1; v1.x += b0; v1.y += b1;
                v0.x = v0.x / (1.0f + expf(-v0.x));
                v0.y = v0.y / (1.0f + expf(-v0.y));
                v1.x = v1.x / (1.0f + expf(-v1.x));
                v1.y = v1.y / (1.0f + expf(-v1.y));
                __half* C = (__half*)Cout;
                *(__half2*)&C[(size_t)rowa * DD + col]       = __floats2half2_rn(v0.x, v0.y);
                *(__half2*)&C[(size_t)(rowa + 8) * DD + col] = __floats2half2_rn(v1.x, v1.y);
            } else {
                float* C = (float*)Cout;
                *(float2*)&C[(size_t)rowa * DD + col]       = v0;
                *(float2*)&C[(size_t)(rowa + 8) * DD + col] = v1;
            }
        }
    }
}

// ---------------- gates: i,f from xconv(fp16); o from x(fp16); smem weights ----
__device__ __forceinline__ float softcapf(float x) {
    return CAPV * tanhf(x * (1.0f / CAPV));
}

__global__ void __launch_bounds__(256)
gates_kernel(const float* __restrict__ ib, const float* __restrict__ fb,
             const float* __restrict__ ob,
             const float* __restrict__ iw, const float* __restrict__ fw,
             const float* __restrict__ ow) {
    __shared__ __half wsm[24 * 1024];      // 48KB: i0-7, f0-7, o0-7

    const int t = threadIdx.x;
    for (int idx = t; idx < 24 * 1024; idx += 256) {
        int gg = idx >> 10, k = idx & 1023;
        float v = (gg < 8) ? iw[gg * 1024 + k]
                : (gg < 16) ? fw[(gg - 8) * 1024 + k]
                            : ow[(gg - 16) * 1024 + k];
        wsm[idx] = __float2half_rn(v);
    }
    __syncthreads();

    const int wid  = t >> 5;
    const int lane = t & 31;

    for (int row = blockIdx.x * 8 + wid; row < BB; row += gridDim.x * 8) {
        const uint4* xc4 = (const uint4*)(g_xch + (size_t)row * 1024);
        const uint4* xx4 = (const uint4*)(g_xh  + (size_t)row * 1024);
        float xcf[32], xxf[32];
#pragma unroll
        for (int j = 0; j < 4; j++) {
            uint4 vc = xc4[lane + j * 32];
            uint4 vx = xx4[lane + j * 32];
            const __half2* hc = (const __half2*)&vc;
            const __half2* hx = (const __half2*)&vx;
#pragma unroll
            for (int q = 0; q < 4; q++) {
                float2 fc = __half22float2(hc[q]);
                float2 fx = __half22float2(hx[q]);
                xcf[j * 8 + q * 2]     = fc.x; xcf[j * 8 + q * 2 + 1] = fc.y;
                xxf[j * 8 + q * 2]     = fx.x; xxf[j * 8 + q * 2 + 1] = fx.y;
            }
        }
#pragma unroll 1
        for (int gg = 0; gg < 24; gg++) {
            const uint4* w4 = (const uint4*)(wsm + gg * 1024);
            const float* xf = (gg < 16) ? xcf : xxf;
            float acc = 0.0f;
#pragma unroll
            for (int j = 0; j < 4; j++) {
                uint4 wv = w4[lane + j * 32];
                const __half2* hw = (const __half2*)&wv;
#pragma unroll
                for (int q = 0; q < 4; q++) {
                    float2 fw2 = __half22float2(hw[q]);
                    acc += xf[j * 8 + q * 2] * fw2.x + xf[j * 8 + q * 2 + 1] * fw2.y;
                }
            }
#pragma unroll
            for (int off = 16; off > 0; off >>= 1)
                acc += __shfl_xor_sync(0xffffffffu, acc, off);
            if (lane == 0) {
                if (gg < 8)       g_it[row * 8 + gg]        = softcapf(acc + ib[gg]);
                else if (gg < 16) g_ft[row * 8 + gg - 8]    = softcapf(acc + fb[gg - 8]);
                else {
                    float vo = softcapf(acc + ob[gg - 16]);
                    g_og[row * 8 + gg - 16] = 1.0f / (1.0f + expf(-vo));
                }
            }
        }
    }
}

// ---------------- gating + per-head LayerNorm (emits h as fp16) ----------------
__global__ void elem_kernel(const float* __restrict__ c, const float* __restrict__ n,
                            const float* __restrict__ m,
                            const float* __restrict__ gw, const float* __restrict__ gb,
                            float* __restrict__ c_out, float* __restrict__ n_out,
                            float* __restrict__ m_out) {
    const int b    = blockIdx.x;
    const int h    = threadIdx.x >> 5;
    const int lane = threadIdx.x & 31;
    const int bh   = b * NHEAD + h;

    float it  = g_it[bh];
    float ft  = g_ft[bh];
    float og  = g_og[bh];
    float m0  = m[bh];
    float fl  = -log1pf(expf(-ft));
    float mn  = fmaxf(fl + m0, it);
    float ig  = expf(it - mn);
    float fg  = expf(fl + m0 - mn);

    size_t base = (size_t)b * 1024 + (size_t)h * 128;

    float hv[4];
    float s = 0.f, sq = 0.f;
#pragma unroll
    for (int j = 0; j < 4; j++) {
        int e = lane + 32 * j;
        float cn = fg * c[base + e] + ig * g_z[base + e];
        float nn = fg * n[base + e] + ig;
        c_out[base + e] = cn;
        n_out[base + e] = nn;
        float x = og * cn / (nn + EPSV);
        hv[j] = x;
        s  += x;
        sq += x * x;
    }
#pragma unroll
    for (int off = 16; off > 0; off >>= 1) {
        s  += __shfl_xor_sync(0xffffffffu, s,  off);
        sq += __shfl_xor_sync(0xffffffffu, sq, off);
    }
    float mu  = s * (1.0f / 128.0f);
    float var = sq * (1.0f / 128.0f) - mu * mu;
    float rs  = rsqrtf(var + EPSV);
#pragma unroll
    for (int j = 0; j < 4; j++) {
        int e = lane + 32 * j;
        float hn = (hv[j] - mu) * rs * gw[h * 128 + e] + gb[h * 128 + e];
        g_hh[base + e] = __float2half_rn(hn);
    }
    if (lane == 0) m_out[bh] = mn;
}

// ---------------- launch --------------------------------------------------------
extern "C" void kernel_launch(void* const* d_in, const int* in_sizes, int n_in,
                              void* d_out, int out_size) {
    const float* x      = (const float*)d_in[0];
    const float* c      = (const float*)d_in[1];
    const float* n      = (const float*)d_in[2];
    const float* m      = (const float*)d_in[3];
    const float* conv_w = (const float*)d_in[4];
    const float* conv_b = (const float*)d_in[5];
    const float* z_w    = (const float*)d_in[6];
    const float* i_w    = (const float*)d_in[7];
    const float* i_b    = (const float*)d_in[8];
    const float* f_w    = (const float*)d_in[9];
    const float* f_b    = (const float*)d_in[10];
    const float* o_w    = (const float*)d_in[11];
    const float* o_b    = (const float*)d_in[12];
    const float* gn_w   = (const float*)d_in[13];
    const float* gn_b   = (const float*)d_in[14];
    const float* out_w  = (const float*)d_in[15];

    float* out   = (float*)d_out;
    float* c_out = out   + (size_t)BB * DD;
    float* n_out = c_out + (size_t)BB * DD;
    float* m_out = n_out + (size_t)BB * DD;

    __half *p_xh, *p_xch, *p_hh;
    __half *p_wchi, *p_wclo, *p_wzhi, *p_wzlo, *p_wohi, *p_wolo;
    float *p_z;
    cudaGetSymbolAddress((void**)&p_xh,   g_xh);
    cudaGetSymbolAddress((void**)&p_xch,  g_xch);
    cudaGetSymbolAddress((void**)&p_hh,   g_hh);
    cudaGetSymbolAddress((void**)&p_wchi, g_wc_hi);
    cudaGetSymbolAddress((void**)&p_wclo, g_wc_lo);
    cudaGetSymbolAddress((void**)&p_wzhi, g_wz_hi);
    cudaGetSymbolAddress((void**)&p_wzlo, g_wz_lo);
    cudaGetSymbolAddress((void**)&p_wohi, g_wo_hi);
    cudaGetSymbolAddress((void**)&p_wolo, g_wo_lo);
    cudaGetSymbolAddress((void**)&p_z,    g_z);

    cudaFuncSetAttribute(gemm2_kernel<0>, cudaFuncAttributeMaxDynamicSharedMemorySize, GEMM_SMEM);
    cudaFuncSetAttribute(gemm2_kernel<1>, cudaFuncAttributeMaxDynamicSharedMemorySize, GEMM_SMEM);

    tohalf_kernel<<<(BB * DD / 8 + 255) / 256, 256>>>(x, p_xh, BB * DD / 8);
    wsplit_conv_kernel<<<(DD * DD + 255) / 256, 256>>>(conv_w);
    wsplit_kernel<<<(DD * DD + 255) / 256, 256>>>(z_w,   p_wzhi, p_wzlo, DD * DD);
    wsplit_kernel<<<(DD * DD + 255) / 256, 256>>>(out_w, p_wohi, p_wolo, DD * DD);

    dim3 gg(DD / 128, BB / 128);   // (8, 256)
    gemm2_kernel<1><<<gg, 256, GEMM_SMEM>>>(p_xh, p_wchi, p_wclo, conv_b, p_xch);  // SiLU(conv) -> fp16
    gemm2_kernel<0><<<gg, 256, GEMM_SMEM>>>(p_xh, p_wzhi, p_wzlo, nullptr, p_z);   // z -> fp32
    gates_kernel<<<592, 256>>>(i_b, f_b, o_b, i_w, f_w, o_w);
    elem_kernel<<<BB, 256>>>(c, n, m, gn_w, gn_b, c_out, n_out, m_out);
    gemm2_kernel<0><<<gg, 256, GEMM_SMEM>>>(p_hh, p_wohi, p_wolo, nullptr, out);   // out -> fp32
}

// round 9
// speedup vs baseline: 5.1722x; 1.0615x over previous
#include <cuda_runtime.h>
#include <cuda_fp16.h>
#include <math.h>
#include <stdint.h>

#define BB   32768
#define DD   1024
#define NHEAD 8
#define KTAP 4
#define EPSV 1e-6f
#define CAPV 15.0f

// ---------------- scratch (allocation-free, __device__ globals) ----------------
__device__ __half g_xh[(size_t)BB * DD];     // x as fp16
__device__ __half g_xch[(size_t)BB * DD];    // SiLU(conv tap) as fp16
__device__ float  g_z[(size_t)BB * DD];      // z projection fp32
__device__ __half g_hh[(size_t)BB * DD];     // h_norm as fp16
__device__ __half g_wc_hi[DD * DD], g_wc_lo[DD * DD];   // conv last tap (lo x1024)
__device__ __half g_wz_hi[DD * DD], g_wz_lo[DD * DD];
__device__ __half g_wo_hi[DD * DD], g_wo_lo[DD * DD];
__device__ float g_it[BB * NHEAD];
__device__ float g_ft[BB * NHEAD];
__device__ float g_og[BB * NHEAD];

// ================= low-level helpers (arch-portable, sm_80+) ===================
__device__ __forceinline__ uint32_t smem_u32(const void* p) {
    uint32_t a;
    asm("{ .reg .u64 t; cvta.to.shared.u64 t, %1; cvt.u32.u64 %0, t; }" : "=r"(a) : "l"(p));
    return a;
}
__device__ __forceinline__ void cp16(uint32_t dst, const void* src) {
    asm volatile("cp.async.cg.shared.global [%0], [%1], 16;" :: "r"(dst), "l"(src));
}
__device__ __forceinline__ void cp_commit() {
    asm volatile("cp.async.commit_group;" ::: "memory");
}
__device__ __forceinline__ void cp_wait0() {
    asm volatile("cp.async.wait_group 0;" ::: "memory");
}
__device__ __forceinline__ void ldsm4(uint32_t* r, uint32_t addr) {
    asm volatile("ldmatrix.sync.aligned.m8n8.x4.shared.b16 {%0,%1,%2,%3}, [%4];"
                 : "=r"(r[0]), "=r"(r[1]), "=r"(r[2]), "=r"(r[3]) : "r"(addr));
}
__device__ __forceinline__ void mma_f16(float* d, const uint32_t* a, const uint32_t* b) {
    asm volatile(
        "mma.sync.aligned.m16n8k16.row.col.f32.f16.f16.f32 "
        "{%0,%1,%2,%3}, {%4,%5,%6,%7}, {%8,%9}, {%0,%1,%2,%3};"
        : "+f"(d[0]), "+f"(d[1]), "+f"(d[2]), "+f"(d[3])
        : "r"(a[0]), "r"(a[1]), "r"(a[2]), "r"(a[3]), "r"(b[0]), "r"(b[1]));
}

// ================= conversion / split kernels ==================================
__global__ void tohalf_kernel(const float* __restrict__ in, __half* __restrict__ out, int n8) {
    int i = blockIdx.x * blockDim.x + threadIdx.x;
    if (i >= n8) return;
    float4 a = ((const float4*)in)[i * 2];
    float4 b = ((const float4*)in)[i * 2 + 1];
    __half2 h[4];
    h[0] = __floats2half2_rn(a.x, a.y);
    h[1] = __floats2half2_rn(a.z, a.w);
    h[2] = __floats2half2_rn(b.x, b.y);
    h[3] = __floats2half2_rn(b.z, b.w);
    ((uint4*)out)[i] = *(uint4*)h;
}

__global__ void wsplit_kernel(const float* __restrict__ w, __half* __restrict__ hi,
                              __half* __restrict__ lo, int n) {
    int i = blockIdx.x * blockDim.x + threadIdx.x;
    if (i >= n) return;
    float v = w[i];
    __half h = __float2half_rn(v);
    hi[i] = h;
    lo[i] = __float2half_rn((v - __half2float(h)) * 1024.0f);
}

__global__ void wsplit_conv_kernel(const float* __restrict__ conv_w) {
    int i = blockIdx.x * blockDim.x + threadIdx.x;
    if (i >= DD * DD) return;
    float v = conv_w[(size_t)i * KTAP + (KTAP - 1)];
    __half h = __float2half_rn(v);
    g_wc_hi[i] = h;
    g_wc_lo[i] = __float2half_rn((v - __half2float(h)) * 1024.0f);
}

// ================= tensor-core GEMM (fp16 2-term: Ah*Whi + (Ah/2^10)*(Wlo*2^10))
// C[M,1024] = A[M,1024] * W[1024,1024]^T. Block 128x128, BK=64, 2 stages,
// single __syncthreads per k-iter, 2 CTAs/SM. 8 warps as 2(M) x 4(N).
// ACT 0: plain fp32 out.  ACT 1: SiLU(y+bias), fp16 out.
#define TSTRIDE   144                     // 128B data + 16B pad (conflict-free)
#define TENSOR_B  (128 * TSTRIDE)         // 18432
#define STAGE_B   (3 * TENSOR_B)          // Ah, Whi, Wlo = 55296
#define NSTAGE    2
#define GEMM_SMEM (NSTAGE * STAGE_B)      // 110592

template <int ACT>
__global__ void __launch_bounds__(256, 2)
gemm2_kernel(const __half* __restrict__ Ah, const __half* __restrict__ Whi,
             const __half* __restrict__ Wlo, const float* __restrict__ bias,
             void* __restrict__ Cout) {
    extern __shared__ char dynsmem[];
    const uint32_t sbase = smem_u32(dynsmem);

    const int t      = threadIdx.x;
    const int lane   = t & 31;
    const int wid    = t >> 5;
    const int warp_m = wid >> 2;
    const int warp_n = wid & 3;
    const int m0     = blockIdx.y * 128;
    const int n0     = blockIdx.x * 128;

    const char* srcs[3];
    srcs[0] = (const char*)(Ah  + (size_t)m0 * DD);
    srcs[1] = (const char*)(Whi + (size_t)n0 * DD);
    srcs[2] = (const char*)(Wlo + (size_t)n0 * DD);

    // 3072 16B chunks per stage (3 tensors x 128 rows x 8 chunks), 12 per thread
    int l_tensor[12], l_row[12], l_ch[12];
#pragma unroll
    for (int j = 0; j < 12; j++) {
        int cid = t + j * 256;
        l_tensor[j] = cid >> 10;
        int rc = cid & 1023;
        l_row[j] = rc >> 3;
        l_ch[j]  = rc & 7;
    }

    auto load_stage = [&](int stg, int kiter) {
        uint32_t sdst = sbase + stg * STAGE_B;
        int k0b = kiter * 128;                // 64 fp16 = 128B along K
#pragma unroll
        for (int j = 0; j < 12; j++) {
            uint32_t dst = sdst + l_tensor[j] * TENSOR_B + l_row[j] * TSTRIDE + l_ch[j] * 16;
            const char* src = srcs[l_tensor[j]] + (size_t)l_row[j] * 2048 + k0b + l_ch[j] * 16;
            cp16(dst, src);
        }
    };

    float acc[4][4][4];
#pragma unroll
    for (int i = 0; i < 4; i++)
#pragma unroll
        for (int j = 0; j < 4; j++)
#pragma unroll
            for (int q = 0; q < 4; q++) acc[i][j][q] = 0.0f;

    const uint32_t offA = (uint32_t)((warp_m * 64 + (lane & 15)) * TSTRIDE + (lane >> 4) * 16);
    const uint32_t offB = (uint32_t)((warp_n * 32 + ((lane >> 4) << 3) + (lane & 7)) * TSTRIDE
                        + (((lane >> 3) & 1) << 4));
    const __half2 dscale = __float2half2_rn(0.0009765625f);   // 2^-10 exact

    load_stage(0, 0);
    cp_commit();

    for (int i = 0; i < 16; i++) {
        cp_wait0();                       // only pending group is load(i)
        __syncthreads();                  // data visible; prev compute done
        if (i + 1 < 16) {
            load_stage((i + 1) & 1, i + 1);
            cp_commit();
        }
        const uint32_t stg = sbase + (i & 1) * STAGE_B;
#pragma unroll
        for (int k16 = 0; k16 < 4; k16++) {
            const uint32_t koff = k16 * 32;
            uint32_t bh[2][4], bl[2][4];
#pragma unroll
            for (int p = 0; p < 2; p++) {
                ldsm4(bh[p], stg + TENSOR_B     + offB + p * (16 * TSTRIDE) + koff);
                ldsm4(bl[p], stg + 2 * TENSOR_B + offB + p * (16 * TSTRIDE) + koff);
            }
#pragma unroll
            for (int mt = 0; mt < 4; mt++) {
                uint32_t ah[4], as[4];
                ldsm4(ah, stg + offA + mt * (16 * TSTRIDE) + koff);
#pragma unroll
                for (int q = 0; q < 4; q++) {
                    __half2 hv = __hmul2(*(__half2*)&ah[q], dscale);
                    as[q] = *(uint32_t*)&hv;
                }
#pragma unroll
                for (int nt = 0; nt < 4; nt++) {
                    const uint32_t* bhp = &bh[nt >> 1][(nt & 1) * 2];
                    const uint32_t* blp = &bl[nt >> 1][(nt & 1) * 2];
                    mma_f16(acc[mt][nt], ah, bhp);
                    mma_f16(acc[mt][nt], as, blp);
                }
            }
        }
    }

    // epilogue straight from fragments
    const int g  = lane >> 2;
    const int tg = lane & 3;
#pragma unroll
    for (int mt = 0; mt < 4; mt++) {
#pragma unroll
        for (int nt = 0; nt < 4; nt++) {
            int col  = n0 + warp_n * 32 + nt * 8 + tg * 2;
            int rowa = m0 + warp_m * 64 + mt * 16 + g;
            float2 v0, v1;
            v0.x = acc[mt][nt][0]; v0.y = acc[mt][nt][1];
            v1.x = acc[mt][nt][2]; v1.y = acc[mt][nt][3];
            if (ACT == 1) {
                float b0 = bias[col], b1 = bias[col + 1];
                v0.x += b0; v0.y += b1; v1.x += b0; v1.y += b1;
                v0.x = v0.x / (1.0f + expf(-v0.x));
                v0.y = v0.y / (1.0f + expf(-v0.y));
                v1.x = v1.x / (1.0f + expf(-v1.x));
                v1.y = v1.y / (1.0f + expf(-v1.y));
                __half* C = (__half*)Cout;
                *(__half2*)&C[(size_t)rowa * DD + col]       = __floats2half2_rn(v0.x, v0.y);
                *(__half2*)&C[(size_t)(rowa + 8) * DD + col] = __floats2half2_rn(v1.x, v1.y);
            } else {
                float* C = (float*)Cout;
                *(float2*)&C[(size_t)rowa * DD + col]       = v0;
                *(float2*)&C[(size_t)(rowa + 8) * DD + col] = v1;
            }
        }
    }
}

// ---------------- gates: i,f from xconv(fp16); o from x(fp16); smem weights ----
__device__ __forceinline__ float softcapf(float x) {
    return CAPV * tanhf(x * (1.0f / CAPV));
}

__global__ void __launch_bounds__(256)
gates_kernel(const float* __restrict__ ib, const float* __restrict__ fb,
             const float* __restrict__ ob,
             const float* __restrict__ iw, const float* __restrict__ fw,
             const float* __restrict__ ow) {
    __shared__ __half wsm[24 * 1024];      // 48KB: i0-7, f0-7, o0-7

    const int t = threadIdx.x;
    for (int idx = t; idx < 24 * 1024; idx += 256) {
        int gg = idx >> 10, k = idx & 1023;
        float v = (gg < 8) ? iw[gg * 1024 + k]
                : (gg < 16) ? fw[(gg - 8) * 1024 + k]
                            : ow[(gg - 16) * 1024 + k];
        wsm[idx] = __float2half_rn(v);
    }
    __syncthreads();

    const int wid  = t >> 5;
    const int lane = t & 31;

    for (int row = blockIdx.x * 8 + wid; row < BB; row += gridDim.x * 8) {
        const uint4* xc4 = (const uint4*)(g_xch + (size_t)row * 1024);
        const uint4* xx4 = (const uint4*)(g_xh  + (size_t)row * 1024);
        float xcf[32], xxf[32];
#pragma unroll
        for (int j = 0; j < 4; j++) {
            uint4 vc = xc4[lane + j * 32];
            uint4 vx = xx4[lane + j * 32];
            const __half2* hc = (const __half2*)&vc;
            const __half2* hx = (const __half2*)&vx;
#pragma unroll
            for (int q = 0; q < 4; q++) {
                float2 fc = __half22float2(hc[q]);
                float2 fx = __half22float2(hx[q]);
                xcf[j * 8 + q * 2]     = fc.x; xcf[j * 8 + q * 2 + 1] = fc.y;
                xxf[j * 8 + q * 2]     = fx.x; xxf[j * 8 + q * 2 + 1] = fx.y;
            }
        }
#pragma unroll 1
        for (int gg = 0; gg < 24; gg++) {
            const uint4* w4 = (const uint4*)(wsm + gg * 1024);
            const float* xf = (gg < 16) ? xcf : xxf;
            float acc = 0.0f;
#pragma unroll
            for (int j = 0; j < 4; j++) {
                uint4 wv = w4[lane + j * 32];
                const __half2* hw = (const __half2*)&wv;
#pragma unroll
                for (int q = 0; q < 4; q++) {
                    float2 fw2 = __half22float2(hw[q]);
                    acc += xf[j * 8 + q * 2] * fw2.x + xf[j * 8 + q * 2 + 1] * fw2.y;
                }
            }
#pragma unroll
            for (int off = 16; off > 0; off >>= 1)
                acc += __shfl_xor_sync(0xffffffffu, acc, off);
            if (lane == 0) {
                if (gg < 8)       g_it[row * 8 + gg]        = softcapf(acc + ib[gg]);
                else if (gg < 16) g_ft[row * 8 + gg - 8]    = softcapf(acc + fb[gg - 8]);
                else {
                    float vo = softcapf(acc + ob[gg - 16]);
                    g_og[row * 8 + gg - 16] = 1.0f / (1.0f + expf(-vo));
                }
            }
        }
    }
}

// ---------------- gating + per-head LayerNorm (emits h as fp16) ----------------
__global__ void elem_kernel(const float* __restrict__ c, const float* __restrict__ n,
                            const float* __restrict__ m,
                            const float* __restrict__ gw, const float* __restrict__ gb,
                            float* __restrict__ c_out, float* __restrict__ n_out,
                            float* __restrict__ m_out) {
    const int b    = blockIdx.x;
    const int h    = threadIdx.x >> 5;
    const int lane = threadIdx.x & 31;
    const int bh   = b * NHEAD + h;

    float it  = g_it[bh];
    float ft  = g_ft[bh];
    float og  = g_og[bh];
    float m0  = m[bh];
    float fl  = -log1pf(expf(-ft));
    float mn  = fmaxf(fl + m0, it);
    float ig  = expf(it - mn);
    float fg  = expf(fl + m0 - mn);

    size_t base = (size_t)b * 1024 + (size_t)h * 128;

    float hv[4];
    float s = 0.f, sq = 0.f;
#pragma unroll
    for (int j = 0; j < 4; j++) {
        int e = lane + 32 * j;
        float cn = fg * c[base + e] + ig * g_z[base + e];
        float nn = fg * n[base + e] + ig;
        c_out[base + e] = cn;
        n_out[base + e] = nn;
        float x = og * cn / (nn + EPSV);
        hv[j] = x;
        s  += x;
        sq += x * x;
    }
#pragma unroll
    for (int off = 16; off > 0; off >>= 1) {
        s  += __shfl_xor_sync(0xffffffffu, s,  off);
        sq += __shfl_xor_sync(0xffffffffu, sq, off);
    }
    float mu  = s * (1.0f / 128.0f);
    float var = sq * (1.0f / 128.0f) - mu * mu;
    float rs  = rsqrtf(var + EPSV);
#pragma unroll
    for (int j = 0; j < 4; j++) {
        int e = lane + 32 * j;
        float hn = (hv[j] - mu) * rs * gw[h * 128 + e] + gb[h * 128 + e];
        g_hh[base + e] = __float2half_rn(hn);
    }
    if (lane == 0) m_out[bh] = mn;
}

// ---------------- launch --------------------------------------------------------
extern "C" void kernel_launch(void* const* d_in, const int* in_sizes, int n_in,
                              void* d_out, int out_size) {
    const float* x      = (const float*)d_in[0];
    const float* c      = (const float*)d_in[1];
    const float* n      = (const float*)d_in[2];
    const float* m      = (const float*)d_in[3];
    const float* conv_w = (const float*)d_in[4];
    const float* conv_b = (const float*)d_in[5];
    const float* z_w    = (const float*)d_in[6];
    const float* i_w    = (const float*)d_in[7];
    const float* i_b    = (const float*)d_in[8];
    const float* f_w    = (const float*)d_in[9];
    const float* f_b    = (const float*)d_in[10];
    const float* o_w    = (const float*)d_in[11];
    const float* o_b    = (const float*)d_in[12];
    const float* gn_w   = (const float*)d_in[13];
    const float* gn_b   = (const float*)d_in[14];
    const float* out_w  = (const float*)d_in[15];

    float* out   = (float*)d_out;
    float* c_out = out   + (size_t)BB * DD;
    float* n_out = c_out + (size_t)BB * DD;
    float* m_out = n_out + (size_t)BB * DD;

    __half *p_xh, *p_xch, *p_hh;
    __half *p_wchi, *p_wclo, *p_wzhi, *p_wzlo, *p_wohi, *p_wolo;
    float *p_z;
    cudaGetSymbolAddress((void**)&p_xh,   g_xh);
    cudaGetSymbolAddress((void**)&p_xch,  g_xch);
    cudaGetSymbolAddress((void**)&p_hh,   g_hh);
    cudaGetSymbolAddress((void**)&p_wchi, g_wc_hi);
    cudaGetSymbolAddress((void**)&p_wclo, g_wc_lo);
    cudaGetSymbolAddress((void**)&p_wzhi, g_wz_hi);
    cudaGetSymbolAddress((void**)&p_wzlo, g_wz_lo);
    cudaGetSymbolAddress((void**)&p_wohi, g_wo_hi);
    cudaGetSymbolAddress((void**)&p_wolo, g_wo_lo);
    cudaGetSymbolAddress((void**)&p_z,    g_z);

    cudaFuncSetAttribute(gemm2_kernel<0>, cudaFuncAttributeMaxDynamicSharedMemorySize, GEMM_SMEM);
    cudaFuncSetAttribute(gemm2_kernel<1>, cudaFuncAttributeMaxDynamicSharedMemorySize, GEMM_SMEM);

    tohalf_kernel<<<(BB * DD / 8 + 255) / 256, 256>>>(x, p_xh, BB * DD / 8);
    wsplit_conv_kernel<<<(DD * DD + 255) / 256, 256>>>(conv_w);
    wsplit_kernel<<<(DD * DD + 255) / 256, 256>>>(z_w,   p_wzhi, p_wzlo, DD * DD);
    wsplit_kernel<<<(DD * DD + 255) / 256, 256>>>(out_w, p_wohi, p_wolo, DD * DD);

    dim3 gg(DD / 128, BB / 128);   // (8, 256)
    gemm2_kernel<1><<<gg, 256, GEMM_SMEM>>>(p_xh, p_wchi, p_wclo, conv_b, p_xch);  // SiLU(conv) -> fp16
    gemm2_kernel<0><<<gg, 256, GEMM_SMEM>>>(p_xh, p_wzhi, p_wzlo, nullptr, p_z);   // z -> fp32
    gates_kernel<<<592, 256>>>(i_b, f_b, o_b, i_w, f_w, o_w);
    elem_kernel<<<BB, 256>>>(c, n, m, gn_w, gn_b, c_out, n_out, m_out);
    gemm2_kernel<0><<<gg, 256, GEMM_SMEM>>>(p_hh, p_wohi, p_wolo, nullptr, out);   // out -> fp32
}

// round 10
// speedup vs baseline: 6.9172x; 1.3374x over previous
#include <cuda_runtime.h>
#include <cuda_fp16.h>
#include <math.h>
#include <stdint.h>

#define BB   32768
#define DD   1024
#define NHEAD 8
#define KTAP 4
#define EPSV 1e-6f
#define CAPV 15.0f

// ---------------- scratch (allocation-free, __device__ globals) ----------------
__device__ __half g_xh[(size_t)BB * DD];     // x as fp16
__device__ __half g_xch[(size_t)BB * DD];    // SiLU(conv tap) as fp16
__device__ __half g_hh[(size_t)BB * DD];     // h_norm as fp16
__device__ __half g_wc_hi[DD * DD];                     // conv last tap (1-term)
__device__ __half g_wz_hi[DD * DD], g_wz_lo[DD * DD];   // z_w (2-term)
__device__ __half g_wo_hi[DD * DD];                     // out_w (1-term)
__device__ float g_it[BB * NHEAD];
__device__ float g_ft[BB * NHEAD];
__device__ float g_og[BB * NHEAD];

// ================= low-level helpers (arch-portable, sm_80+) ===================
__device__ __forceinline__ uint32_t smem_u32(const void* p) {
    uint32_t a;
    asm("{ .reg .u64 t; cvta.to.shared.u64 t, %1; cvt.u32.u64 %0, t; }" : "=r"(a) : "l"(p));
    return a;
}
__device__ __forceinline__ void cp16(uint32_t dst, const void* src) {
    asm volatile("cp.async.cg.shared.global [%0], [%1], 16;" :: "r"(dst), "l"(src));
}
__device__ __forceinline__ void cp_commit() {
    asm volatile("cp.async.commit_group;" ::: "memory");
}
__device__ __forceinline__ void cp_wait0() {
    asm volatile("cp.async.wait_group 0;" ::: "memory");
}
__device__ __forceinline__ void ldsm4(uint32_t* r, uint32_t addr) {
    asm volatile("ldmatrix.sync.aligned.m8n8.x4.shared.b16 {%0,%1,%2,%3}, [%4];"
                 : "=r"(r[0]), "=r"(r[1]), "=r"(r[2]), "=r"(r[3]) : "r"(addr));
}
__device__ __forceinline__ void mma_f16(float* d, const uint32_t* a, const uint32_t* b) {
    asm volatile(
        "mma.sync.aligned.m16n8k16.row.col.f32.f16.f16.f32 "
        "{%0,%1,%2,%3}, {%4,%5,%6,%7}, {%8,%9}, {%0,%1,%2,%3};"
        : "+f"(d[0]), "+f"(d[1]), "+f"(d[2]), "+f"(d[3])
        : "r"(a[0]), "r"(a[1]), "r"(a[2]), "r"(a[3]), "r"(b[0]), "r"(b[1]));
}

// ================= conversion / split kernels ==================================
__global__ void tohalf_kernel(const float* __restrict__ in, __half* __restrict__ out, int n8) {
    int i = blockIdx.x * blockDim.x + threadIdx.x;
    if (i >= n8) return;
    float4 a = ((const float4*)in)[i * 2];
    float4 b = ((const float4*)in)[i * 2 + 1];
    __half2 h[4];
    h[0] = __floats2half2_rn(a.x, a.y);
    h[1] = __floats2half2_rn(a.z, a.w);
    h[2] = __floats2half2_rn(b.x, b.y);
    h[3] = __floats2half2_rn(b.z, b.w);
    ((uint4*)out)[i] = *(uint4*)h;
}

__global__ void wsplit_kernel(const float* __restrict__ w, __half* __restrict__ hi,
                              __half* __restrict__ lo, int n) {
    int i = blockIdx.x * blockDim.x + threadIdx.x;
    if (i >= n) return;
    float v = w[i];
    __half h = __float2half_rn(v);
    hi[i] = h;
    lo[i] = __float2half_rn((v - __half2float(h)) * 1024.0f);
}

__global__ void wconv_kernel(const float* __restrict__ conv_w) {
    int i = blockIdx.x * blockDim.x + threadIdx.x;
    if (i >= DD * DD) return;
    g_wc_hi[i] = __float2half_rn(conv_w[(size_t)i * KTAP + (KTAP - 1)]);
}

// ================= tensor-core GEMM =============================================
// C[M,1024] = A[M,1024] * W[1024,1024]^T, fp16 operands, fp32 accum.
// NTERMS=2 adds (Ah*2^-10)*(Wlo*2^10) error compensation.
// MODE 0: fp32 out. MODE 1: SiLU(y+bias) -> fp16 out.
// MODE 2: fused sLSTM gating + per-head LayerNorm epilogue (tile = one head).
#define TSTRIDE   144                     // 128B data + 16B pad (conflict-free)
#define TENSOR_B  (128 * TSTRIDE)         // 18432
#define STAGE_B   (3 * TENSOR_B)          // slots: Ah, Whi, (Wlo)
#define NSTAGE    2
#define GEMM_SMEM (NSTAGE * STAGE_B)      // 110592

template <int MODE, int NTERMS>
__global__ void __launch_bounds__(256, 2)
gemm2_kernel(const __half* __restrict__ Ah, const __half* __restrict__ Whi,
             const __half* __restrict__ Wlo, const float* __restrict__ bias,
             void* __restrict__ Cout,
             const float* __restrict__ cc, const float* __restrict__ nn_,
             const float* __restrict__ mm_,
             const float* __restrict__ gw, const float* __restrict__ gb,
             float* __restrict__ c_out, float* __restrict__ n_out,
             float* __restrict__ m_out) {
    extern __shared__ char dynsmem[];
    const uint32_t sbase = smem_u32(dynsmem);

    const int t      = threadIdx.x;
    const int lane   = t & 31;
    const int wid    = t >> 5;
    const int warp_m = wid >> 2;
    const int warp_n = wid & 3;
    const int m0     = blockIdx.y * 128;
    const int n0     = blockIdx.x * 128;

    const char* srcs[3];
    srcs[0] = (const char*)(Ah  + (size_t)m0 * DD);
    srcs[1] = (const char*)(Whi + (size_t)n0 * DD);
    srcs[2] = (const char*)(NTERMS == 2 ? (Wlo + (size_t)n0 * DD) : (const __half*)0);

    constexpr int NCHUNK = (NTERMS == 2) ? 12 : 8;   // 16B chunks per thread/stage
    int l_tensor[NCHUNK], l_row[NCHUNK], l_ch[NCHUNK];
#pragma unroll
    for (int j = 0; j < NCHUNK; j++) {
        int cid = t + j * 256;
        l_tensor[j] = cid >> 10;
        int rc = cid & 1023;
        l_row[j] = rc >> 3;
        l_ch[j]  = rc & 7;
    }

    auto load_stage = [&](int stg, int kiter) {
        uint32_t sdst = sbase + stg * STAGE_B;
        int k0b = kiter * 128;                // 64 fp16 = 128B along K
#pragma unroll
        for (int j = 0; j < NCHUNK; j++) {
            uint32_t dst = sdst + l_tensor[j] * TENSOR_B + l_row[j] * TSTRIDE + l_ch[j] * 16;
            const char* src = srcs[l_tensor[j]] + (size_t)l_row[j] * 2048 + k0b + l_ch[j] * 16;
            cp16(dst, src);
        }
    };

    float acc[4][4][4];
#pragma unroll
    for (int i = 0; i < 4; i++)
#pragma unroll
        for (int j = 0; j < 4; j++)
#pragma unroll
            for (int q = 0; q < 4; q++) acc[i][j][q] = 0.0f;

    const uint32_t offA = (uint32_t)((warp_m * 64 + (lane & 15)) * TSTRIDE + (lane >> 4) * 16);
    const uint32_t offB = (uint32_t)((warp_n * 32 + ((lane >> 4) << 3) + (lane & 7)) * TSTRIDE
                        + (((lane >> 3) & 1) << 4));
    const __half2 dscale = __float2half2_rn(0.0009765625f);   // 2^-10 exact

    load_stage(0, 0);
    cp_commit();

    for (int i = 0; i < 16; i++) {
        cp_wait0();
        __syncthreads();
        if (i + 1 < 16) {
            load_stage((i + 1) & 1, i + 1);
            cp_commit();
        }
        const uint32_t stg = sbase + (i & 1) * STAGE_B;
#pragma unroll
        for (int k16 = 0; k16 < 4; k16++) {
            const uint32_t koff = k16 * 32;
            uint32_t bh[2][4], bl[2][4];
#pragma unroll
            for (int p = 0; p < 2; p++) {
                ldsm4(bh[p], stg + TENSOR_B + offB + p * (16 * TSTRIDE) + koff);
                if (NTERMS == 2)
                    ldsm4(bl[p], stg + 2 * TENSOR_B + offB + p * (16 * TSTRIDE) + koff);
            }
#pragma unroll
            for (int mt = 0; mt < 4; mt++) {
                uint32_t ah[4], as[4];
                ldsm4(ah, stg + offA + mt * (16 * TSTRIDE) + koff);
                if (NTERMS == 2) {
#pragma unroll
                    for (int q = 0; q < 4; q++) {
                        __half2 hv = __hmul2(*(__half2*)&ah[q], dscale);
                        as[q] = *(uint32_t*)&hv;
                    }
                }
#pragma unroll
                for (int nt = 0; nt < 4; nt++) {
                    const uint32_t* bhp = &bh[nt >> 1][(nt & 1) * 2];
                    mma_f16(acc[mt][nt], ah, bhp);
                    if (NTERMS == 2) {
                        const uint32_t* blp = &bl[nt >> 1][(nt & 1) * 2];
                        mma_f16(acc[mt][nt], as, blp);
                    }
                }
            }
        }
    }

    const int g  = lane >> 2;
    const int tg = lane & 3;

    if (MODE == 2) {
        // ======== fused gating + per-head LayerNorm epilogue ====================
        // tile n-range [n0, n0+128) is exactly head hidx = blockIdx.x
        const int hidx = blockIdx.x;
        float* ep    = (float*)dynsmem;
        float* sig   = ep;            // [128] i gate (exp)
        float* sfg   = ep + 128;      // [128] f gate (exp)
        float* sog   = ep + 256;      // [128] o gate (sigmoid)
        float* gwsm  = ep + 384;      // [128]
        float* gbsm  = ep + 512;      // [128]
        float* rsum  = ep + 640;      // [4][128]
        float* rsq   = ep + 1152;     // [4][128]

        __syncthreads();              // mainloop smem dead
        if (t < 128) {
            int bh_i = (m0 + t) * 8 + hidx;
            float it  = g_it[bh_i];
            float ft  = g_ft[bh_i];
            float m0v = mm_[bh_i];
            float fl  = -log1pf(expf(-ft));
            float mn  = fmaxf(fl + m0v, it);
            sig[t] = expf(it - mn);
            sfg[t] = expf(fl + m0v - mn);
            sog[t] = g_og[bh_i];
            m_out[bh_i] = mn;
        } else {
            int e = t - 128;
            gwsm[e] = gw[hidx * 128 + e];
            gbsm[e] = gb[hidx * 128 + e];
        }
        __syncthreads();

        // phase 1: c_new/n_new, h, partial row sums
#pragma unroll
        for (int mt = 0; mt < 4; mt++) {
#pragma unroll
            for (int hf = 0; hf < 2; hf++) {
                int r = warp_m * 64 + mt * 16 + g + hf * 8;
                float igv = sig[r], fgv = sfg[r], ogv = sog[r];
                size_t rowbase = (size_t)(m0 + r) * 1024 + hidx * 128;
                float s = 0.f, sq = 0.f;
#pragma unroll
                for (int nt = 0; nt < 4; nt++) {
                    int e = warp_n * 32 + nt * 8 + tg * 2;
                    float2 cv = *(const float2*)&cc[rowbase + e];
                    float2 nv = *(const float2*)&nn_[rowbase + e];
                    float z0 = acc[mt][nt][hf * 2 + 0];
                    float z1 = acc[mt][nt][hf * 2 + 1];
                    float cn0 = fgv * cv.x + igv * z0;
                    float cn1 = fgv * cv.y + igv * z1;
                    float nn0 = fgv * nv.x + igv;
                    float nn1 = fgv * nv.y + igv;
                    *(float2*)&c_out[rowbase + e] = make_float2(cn0, cn1);
                    *(float2*)&n_out[rowbase + e] = make_float2(nn0, nn1);
                    float h0 = ogv * cn0 / (nn0 + EPSV);
                    float h1 = ogv * cn1 / (nn1 + EPSV);
                    acc[mt][nt][hf * 2 + 0] = h0;
                    acc[mt][nt][hf * 2 + 1] = h1;
                    s += h0 + h1;
                    sq += h0 * h0 + h1 * h1;
                }
                s  += __shfl_xor_sync(0xffffffffu, s, 1);
                s  += __shfl_xor_sync(0xffffffffu, s, 2);
                sq += __shfl_xor_sync(0xffffffffu, sq, 1);
                sq += __shfl_xor_sync(0xffffffffu, sq, 2);
                if (tg == 0) {
                    rsum[warp_n * 128 + r] = s;
                    rsq[warp_n * 128 + r]  = sq;
                }
            }
        }
        __syncthreads();

        // phase 2: normalize + affine -> fp16 h
#pragma unroll
        for (int mt = 0; mt < 4; mt++) {
#pragma unroll
            for (int hf = 0; hf < 2; hf++) {
                int r = warp_m * 64 + mt * 16 + g + hf * 8;
                float s  = rsum[r] + rsum[128 + r] + rsum[256 + r] + rsum[384 + r];
                float sq = rsq[r]  + rsq[128 + r]  + rsq[256 + r]  + rsq[384 + r];
                float mu  = s * (1.0f / 128.0f);
                float var = sq * (1.0f / 128.0f) - mu * mu;
                float rs  = rsqrtf(var + EPSV);
                size_t rowbase = (size_t)(m0 + r) * 1024 + hidx * 128;
#pragma unroll
                for (int nt = 0; nt < 4; nt++) {
                    int e = warp_n * 32 + nt * 8 + tg * 2;
                    float h0 = (acc[mt][nt][hf * 2 + 0] - mu) * rs * gwsm[e]     + gbsm[e];
                    float h1 = (acc[mt][nt][hf * 2 + 1] - mu) * rs * gwsm[e + 1] + gbsm[e + 1];
                    *(__half2*)&g_hh[rowbase + e] = __floats2half2_rn(h0, h1);
                }
            }
        }
    } else {
        // ======== plain / SiLU epilogue =========================================
#pragma unroll
        for (int mt = 0; mt < 4; mt++) {
#pragma unroll
            for (int nt = 0; nt < 4; nt++) {
                int col  = n0 + warp_n * 32 + nt * 8 + tg * 2;
                int rowa = m0 + warp_m * 64 + mt * 16 + g;
                float2 v0, v1;
                v0.x = acc[mt][nt][0]; v0.y = acc[mt][nt][1];
                v1.x = acc[mt][nt][2]; v1.y = acc[mt][nt][3];
                if (MODE == 1) {
                    float b0 = bias[col], b1 = bias[col + 1];
                    v0.x += b0; v0.y += b1; v1.x += b0; v1.y += b1;
                    v0.x = v0.x / (1.0f + expf(-v0.x));
                    v0.y = v0.y / (1.0f + expf(-v0.y));
                    v1.x = v1.x / (1.0f + expf(-v1.x));
                    v1.y = v1.y / (1.0f + expf(-v1.y));
                    __half* C = (__half*)Cout;
                    *(__half2*)&C[(size_t)rowa * DD + col]       = __floats2half2_rn(v0.x, v0.y);
                    *(__half2*)&C[(size_t)(rowa + 8) * DD + col] = __floats2half2_rn(v1.x, v1.y);
                } else {
                    float* C = (float*)Cout;
                    *(float2*)&C[(size_t)rowa * DD + col]       = v0;
                    *(float2*)&C[(size_t)(rowa + 8) * DD + col] = v1;
                }
            }
        }
    }
}

// ---------------- gates: i,f from xconv(fp16); o from x(fp16); smem weights ----
__device__ __forceinline__ float softcapf(float x) {
    return CAPV * tanhf(x * (1.0f / CAPV));
}

__global__ void __launch_bounds__(256)
gates_kernel(const float* __restrict__ ib, const float* __restrict__ fb,
             const float* __restrict__ ob,
             const float* __restrict__ iw, const float* __restrict__ fw,
             const float* __restrict__ ow) {
    __shared__ __half wsm[24 * 1024];      // 48KB: i0-7, f0-7, o0-7

    const int t = threadIdx.x;
    for (int idx = t; idx < 24 * 1024; idx += 256) {
        int gg = idx >> 10, k = idx & 1023;
        float v = (gg < 8) ? iw[gg * 1024 + k]
                : (gg < 16) ? fw[(gg - 8) * 1024 + k]
                            : ow[(gg - 16) * 1024 + k];
        wsm[idx] = __float2half_rn(v);
    }
    __syncthreads();

    const int wid  = t >> 5;
    const int lane = t & 31;

    for (int row = blockIdx.x * 8 + wid; row < BB; row += gridDim.x * 8) {
        const uint4* xc4 = (const uint4*)(g_xch + (size_t)row * 1024);
        const uint4* xx4 = (const uint4*)(g_xh  + (size_t)row * 1024);
        float xcf[32], xxf[32];
#pragma unroll
        for (int j = 0; j < 4; j++) {
            uint4 vc = xc4[lane + j * 32];
            uint4 vx = xx4[lane + j * 32];
            const __half2* hc = (const __half2*)&vc;
            const __half2* hx = (const __half2*)&vx;
#pragma unroll
            for (int q = 0; q < 4; q++) {
                float2 fc = __half22float2(hc[q]);
                float2 fx = __half22float2(hx[q]);
                xcf[j * 8 + q * 2]     = fc.x; xcf[j * 8 + q * 2 + 1] = fc.y;
                xxf[j * 8 + q * 2]     = fx.x; xxf[j * 8 + q * 2 + 1] = fx.y;
            }
        }
#pragma unroll 1
        for (int gg = 0; gg < 24; gg++) {
            const uint4* w4 = (const uint4*)(wsm + gg * 1024);
            const float* xf = (gg < 16) ? xcf : xxf;
            float acc = 0.0f;
#pragma unroll
            for (int j = 0; j < 4; j++) {
                uint4 wv = w4[lane + j * 32];
                const __half2* hw = (const __half2*)&wv;
#pragma unroll
                for (int q = 0; q < 4; q++) {
                    float2 fw2 = __half22float2(hw[q]);
                    acc += xf[j * 8 + q * 2] * fw2.x + xf[j * 8 + q * 2 + 1] * fw2.y;
                }
            }
#pragma unroll
            for (int off = 16; off > 0; off >>= 1)
                acc += __shfl_xor_sync(0xffffffffu, acc, off);
            if (lane == 0) {
                if (gg < 8)       g_it[row * 8 + gg]        = softcapf(acc + ib[gg]);
                else if (gg < 16) g_ft[row * 8 + gg - 8]    = softcapf(acc + fb[gg - 8]);
                else {
                    float vo = softcapf(acc + ob[gg - 16]);
                    g_og[row * 8 + gg - 16] = 1.0f / (1.0f + expf(-vo));
                }
            }
        }
    }
}

// ---------------- launch --------------------------------------------------------
extern "C" void kernel_launch(void* const* d_in, const int* in_sizes, int n_in,
                              void* d_out, int out_size) {
    const float* x      = (const float*)d_in[0];
    const float* c      = (const float*)d_in[1];
    const float* n      = (const float*)d_in[2];
    const float* m      = (const float*)d_in[3];
    const float* conv_w = (const float*)d_in[4];
    const float* conv_b = (const float*)d_in[5];
    const float* z_w    = (const float*)d_in[6];
    const float* i_w    = (const float*)d_in[7];
    const float* i_b    = (const float*)d_in[8];
    const float* f_w    = (const float*)d_in[9];
    const float* f_b    = (const float*)d_in[10];
    const float* o_w    = (const float*)d_in[11];
    const float* o_b    = (const float*)d_in[12];
    const float* gn_w   = (const float*)d_in[13];
    const float* gn_b   = (const float*)d_in[14];
    const float* out_w  = (const float*)d_in[15];

    float* out   = (float*)d_out;
    float* c_out = out   + (size_t)BB * DD;
    float* n_out = c_out + (size_t)BB * DD;
    float* m_out = n_out + (size_t)BB * DD;

    __half *p_xh, *p_xch, *p_hh, *p_wchi, *p_wzhi, *p_wzlo, *p_wohi;
    cudaGetSymbolAddress((void**)&p_xh,   g_xh);
    cudaGetSymbolAddress((void**)&p_xch,  g_xch);
    cudaGetSymbolAddress((void**)&p_hh,   g_hh);
    cudaGetSymbolAddress((void**)&p_wchi, g_wc_hi);
    cudaGetSymbolAddress((void**)&p_wzhi, g_wz_hi);
    cudaGetSymbolAddress((void**)&p_wzlo, g_wz_lo);
    cudaGetSymbolAddress((void**)&p_wohi, g_wo_hi);

    cudaFuncSetAttribute((const void*)gemm2_kernel<1, 1>, cudaFuncAttributeMaxDynamicSharedMemorySize, GEMM_SMEM);
    cudaFuncSetAttribute((const void*)gemm2_kernel<2, 2>, cudaFuncAttributeMaxDynamicSharedMemorySize, GEMM_SMEM);
    cudaFuncSetAttribute((const void*)gemm2_kernel<0, 1>, cudaFuncAttributeMaxDynamicSharedMemorySize, GEMM_SMEM);

    tohalf_kernel<<<(BB * DD / 8 + 255) / 256, 256>>>(x, p_xh, BB * DD / 8);
    wconv_kernel<<<(DD * DD + 255) / 256, 256>>>(conv_w);
    wsplit_kernel<<<(DD * DD + 255) / 256, 256>>>(z_w, p_wzhi, p_wzlo, DD * DD);
    tohalf_kernel<<<(DD * DD / 8 + 255) / 256, 256>>>(out_w, p_wohi, DD * DD / 8);

    dim3 gg(DD / 128, BB / 128);   // (8, 256)

    // conv GEMM (1-term) -> SiLU -> fp16 xconv
    gemm2_kernel<1, 1><<<gg, 256, GEMM_SMEM>>>(
        p_xh, p_wchi, nullptr, conv_b, p_xch,
        nullptr, nullptr, nullptr, nullptr, nullptr, nullptr, nullptr, nullptr);
    // gate projections
    gates_kernel<<<592, 256>>>(i_b, f_b, o_b, i_w, f_w, o_w);
    // z GEMM (2-term) + fused gating/LayerNorm epilogue
    gemm2_kernel<2, 2><<<gg, 256, GEMM_SMEM>>>(
        p_xh, p_wzhi, p_wzlo, nullptr, nullptr,
        c, n, m, gn_w, gn_b, c_out, n_out, m_out);
    // out projection (1-term) -> fp32
    gemm2_kernel<0, 1><<<gg, 256, GEMM_SMEM>>>(
        p_hh, p_wohi, nullptr, nullptr, out,
        nullptr, nullptr, nullptr, nullptr, nullptr, nullptr, nullptr, nullptr);
}